// round 17
// baseline (speedup 1.0000x reference)
#include <cuda_runtime.h>
#include <cuda_bf16.h>
#include <math.h>

typedef unsigned long long ull;

// Problem constants
#define Bz   64
#define Tz   1024
#define Dz   128
#define Hz   512
#define Gz   2048          // 4*H
#define BT   65536         // B*T
#define NCHUNK 256         // bn partial chunks

// ---------------- scratch (device globals; no cudaMalloc allowed) ----------
__device__ float    g_xg[(size_t)Tz * Bz * Gz];   // [T][B][4H]
__device__ float    g_h1[(size_t)BT * Hz];        // [B][T][H]
__device__ float    g_h2[(size_t)BT * Hz];        // [B][T][H]
__device__ __align__(16) __nv_bfloat16 g_hhi[2][Bz * Hz];  // recurrent h hi plane (ping-pong)
__device__ __align__(16) __nv_bfloat16 g_hlo[2][Bz * Hz];  // recurrent h lo plane
__device__ unsigned g_barG[4 * 32];               // 4 group counters, 128B apart
__device__ float    g_ps [NCHUNK * Hz];           // BN partial sums
__device__ float    g_ps2[NCHUNK * Hz];
__device__ float    g_bnA[Hz];                    // folded BN scale
__device__ float    g_bnB[Hz];                    // folded BN bias
// packed GEMM operands: [block][chunk][hi 16KB | lo 16KB], XOR-swizzled
__device__ __align__(128) char g_Apk[(size_t)512 * 8 * 32768];   // 128 MB (max layer2)
__device__ __align__(128) char g_Wpk[(size_t)16  * 8 * 32768];   // 4 MB
// flat W^T planes for the recurrence (unchanged)
__device__ __nv_bfloat16  g_WhiT[(size_t)Gz * Hz];
__device__ __nv_bfloat16  g_WloT[(size_t)Gz * Hz];

// ---------------- helpers ---------------------------------------------------
#define CP_ASYNC16(saddr, gptr) \
    asm volatile("cp.async.cg.shared.global [%0], [%1], 16;" :: "r"(saddr), "l"(gptr))
#define CP_COMMIT() asm volatile("cp.async.commit_group;")
#define CP_WAIT0()  asm volatile("cp.async.wait_group 0;")

#define MBARRIER_INIT(addr, cnt) \
    asm volatile("mbarrier.init.shared.b64 [%0], %1;" :: "r"(addr), "r"(cnt) : "memory")
#define MBARRIER_EXPECT_TX(addr, bytes) \
    asm volatile("mbarrier.arrive.expect_tx.shared.b64 _, [%0], %1;" :: "r"(addr), "r"(bytes) : "memory")
#define MBARRIER_WAIT(addr, parity) do {                                          \
    asm volatile(                                                                 \
        "{\n\t.reg .pred P1;\n\t"                                                 \
        "WL_%=:\n\t"                                                              \
        "mbarrier.try_wait.parity.acquire.cta.shared::cta.b64 P1, [%0], %1, 0x989680;\n\t" \
        "@P1 bra.uni WD_%=;\n\t"                                                  \
        "bra.uni WL_%=;\n\t"                                                      \
        "WD_%=:\n\t}"                                                             \
        :: "r"(addr), "r"(parity) : "memory");                                    \
} while (0)

#define BULK_G2S(dst, src, bytes, mbar) \
    asm volatile("cp.async.bulk.shared::cta.global.mbarrier::complete_tx::bytes [%0], [%1], %2, [%3];" \
                 :: "r"(dst), "l"(src), "r"(bytes), "r"(mbar) : "memory")

__device__ __forceinline__ void mma_bf16(float* c, const unsigned* a, const unsigned* b)
{
    asm volatile(
        "mma.sync.aligned.m16n8k16.row.col.f32.bf16.bf16.f32 "
        "{%0,%1,%2,%3}, {%4,%5,%6,%7}, {%8,%9}, {%0,%1,%2,%3};"
        : "+f"(c[0]), "+f"(c[1]), "+f"(c[2]), "+f"(c[3])
        : "r"(a[0]), "r"(a[1]), "r"(a[2]), "r"(a[3]), "r"(b[0]), "r"(b[1]));
}

// packed-plane byte offset for (row 0..127, local k col 0..63)
__device__ __forceinline__ unsigned pk_off(int row, int kl) {
    return (unsigned)(row * 128 + (((kl >> 3) ^ (row & 7)) << 4) + ((kl & 7) << 1));
}

// ---------------------------------------------------------------------------
// split_A / split_A_bn: fp32 -> packed bf16 hi/lo blocks. (proven)
// ---------------------------------------------------------------------------
__device__ __forceinline__ void split_store(int m, int k, int nk, float4 v)
{
    __nv_bfloat162 h01 = __floats2bfloat162_rn(v.x, v.y);
    __nv_bfloat162 h23 = __floats2bfloat162_rn(v.z, v.w);
    float lx = v.x - __bfloat162float(h01.x);
    float ly = v.y - __bfloat162float(h01.y);
    float lz = v.z - __bfloat162float(h23.x);
    float lw = v.w - __bfloat162float(h23.y);
    __nv_bfloat162 l01 = __floats2bfloat162_rn(lx, ly);
    __nv_bfloat162 l23 = __floats2bfloat162_rn(lz, lw);
    int mb = m >> 7, row = m & 127, ck = k >> 6, kl = k & 63;
    char* blk = g_Apk + ((size_t)(mb * nk + ck)) * 32768;
    unsigned off = pk_off(row, kl);
    *reinterpret_cast<uint2*>(blk + off) =
        make_uint2(*reinterpret_cast<unsigned*>(&h01), *reinterpret_cast<unsigned*>(&h23));
    *reinterpret_cast<uint2*>(blk + 16384 + off) =
        make_uint2(*reinterpret_cast<unsigned*>(&l01), *reinterpret_cast<unsigned*>(&l23));
}

__global__ void split_A(const float* __restrict__ src, int n4, int ksh, int nk)
{
    int idx = blockIdx.x * 256 + threadIdx.x;
    if (idx >= n4) return;
    float4 v = reinterpret_cast<const float4*>(src)[idx];
    int m = idx >> ksh;
    int k = (idx & ((1 << ksh) - 1)) << 2;
    split_store(m, k, nk, v);
}

__global__ void split_A_bn(const float* __restrict__ src, int n4, int ksh, int nk)
{
    int idx = blockIdx.x * 256 + threadIdx.x;
    if (idx >= n4) return;
    float4 v = reinterpret_cast<const float4*>(src)[idx];
    int f = (idx & 127) * 4;                 // valid for K=H=512 (layer 2 only)
    float4 a = *reinterpret_cast<const float4*>(&g_bnA[f]);
    float4 b = *reinterpret_cast<const float4*>(&g_bnB[f]);
    v.x = v.x * a.x + b.x;
    v.y = v.y * a.y + b.y;
    v.z = v.z * a.z + b.z;
    v.w = v.w * a.w + b.w;
    int m = idx >> ksh;
    int k = (idx & ((1 << ksh) - 1)) << 2;
    split_store(m, k, nk, v);
}

// split_W_pk: W [K][2048] -> packed W^T blocks (proven)
__global__ void split_W_pk(const float* __restrict__ W, int K, int nk)
{
    int idx = blockIdx.x * 256 + threadIdx.x;
    int kq = K >> 2;
    if (idx >= Gz * kq) return;
    int n = idx / kq;
    int k = (idx % kq) << 2;
    float4 v;
    v.x = W[(size_t)(k + 0) * Gz + n];
    v.y = W[(size_t)(k + 1) * Gz + n];
    v.z = W[(size_t)(k + 2) * Gz + n];
    v.w = W[(size_t)(k + 3) * Gz + n];
    __nv_bfloat162 h01 = __floats2bfloat162_rn(v.x, v.y);
    __nv_bfloat162 h23 = __floats2bfloat162_rn(v.z, v.w);
    float lx = v.x - __bfloat162float(h01.x);
    float ly = v.y - __bfloat162float(h01.y);
    float lz = v.z - __bfloat162float(h23.x);
    float lw = v.w - __bfloat162float(h23.y);
    __nv_bfloat162 l01 = __floats2bfloat162_rn(lx, ly);
    __nv_bfloat162 l23 = __floats2bfloat162_rn(lz, lw);
    int nb = n >> 7, row = n & 127, ck = k >> 6, kl = k & 63;
    char* blk = g_Wpk + ((size_t)(nb * nk + ck)) * 32768;
    unsigned off = pk_off(row, kl);
    *reinterpret_cast<uint2*>(blk + off) =
        make_uint2(*reinterpret_cast<unsigned*>(&h01), *reinterpret_cast<unsigned*>(&h23));
    *reinterpret_cast<uint2*>(blk + 16384 + off) =
        make_uint2(*reinterpret_cast<unsigned*>(&l01), *reinterpret_cast<unsigned*>(&l23));
}

// split_W flat (recurrence weights) — verbatim
__global__ void split_W(const float* __restrict__ W, int K)
{
    __shared__ float tile[32][33];
    int bx = blockIdx.x;
    int by = blockIdx.y;
    int tx = threadIdx.x & 31, ty = threadIdx.x >> 5;
#pragma unroll
    for (int i = 0; i < 4; i++)
        tile[ty + i * 8][tx] = W[(size_t)(by * 32 + ty + i * 8) * Gz + bx * 32 + tx];
    __syncthreads();
#pragma unroll
    for (int i = 0; i < 4; i++) {
        int n = bx * 32 + ty + i * 8;
        int k = by * 32 + tx;
        float v = tile[tx][ty + i * 8];
        __nv_bfloat16 h = __float2bfloat16(v);
        g_WhiT[(size_t)n * K + k] = h;
        g_WloT[(size_t)n * K + k] = __float2bfloat16(v - __bfloat162float(h));
    }
}

// ---------------------------------------------------------------------------
// bf16 3-pass GEMM v4 (bulk-copy, proven).
// ---------------------------------------------------------------------------
#define GSTAGE_BYTES 65536
#define GEMM_SMEM (1024 + 3 * GSTAGE_BYTES)   // 197632 B

__global__ __launch_bounds__(512, 1) void sgemm_bf16(
    const float* __restrict__ bias, float* __restrict__ out, int K)
{
    extern __shared__ unsigned sgw[];

    const int tid  = threadIdx.x;
    const int cCol = blockIdx.x;
    const int cRow = blockIdx.y;

    unsigned sbase;
    {
        unsigned long long t64;
        asm("cvta.to.shared.u64 %0, %1;" : "=l"(t64) : "l"(sgw));
        sbase = (unsigned)t64;
    }
    const unsigned dataB = sbase + 1024u;
    const int nk = K >> 6;

    if (tid == 0) {
        MBARRIER_INIT(sbase + 16, 1);
        MBARRIER_INIT(sbase + 24, 1);
        MBARRIER_INIT(sbase + 32, 1);
    }
    __syncthreads();

    const char* Asrc = g_Apk + (size_t)cRow * nk * 32768;
    const char* Bsrc = g_Wpk + (size_t)cCol * nk * 32768;

    auto issue = [&](int ci, int st) {
        unsigned mb = sbase + 16u + (unsigned)st * 8u;
        unsigned dst = dataB + (unsigned)st * GSTAGE_BYTES;
        MBARRIER_EXPECT_TX(mb, 65536u);
        BULK_G2S(dst,          Asrc + (size_t)ci * 32768, 32768u, mb);
        BULK_G2S(dst + 32768u, Bsrc + (size_t)ci * 32768, 32768u, mb);
    };

    if (tid == 0) {
        issue(0, 0);
        if (nk > 1) issue(1, 1);
        if (nk > 2) issue(2, 2);
    }

    const int wid  = tid >> 5;
    const int lane = tid & 31;
    const int wm   = (wid >> 2) * 32;
    const int wn   = (wid & 3) * 32;
    const int lg   = lane >> 2;
    const int lc   = lane & 3;

    float acc[2][4][4];
#pragma unroll
    for (int i = 0; i < 2; i++)
#pragma unroll
        for (int j = 0; j < 4; j++)
#pragma unroll
            for (int r = 0; r < 4; r++) acc[i][j][r] = 0.f;

    int ph0 = 0, ph1 = 0, ph2 = 0;

    for (int ci = 0; ci < nk; ci++) {
        const int st = ci % 3;
        if (st == 0)      { MBARRIER_WAIT(sbase + 16, ph0); ph0 ^= 1; }
        else if (st == 1) { MBARRIER_WAIT(sbase + 24, ph1); ph1 ^= 1; }
        else              { MBARRIER_WAIT(sbase + 32, ph2); ph2 ^= 1; }

        const unsigned* As_hi = sgw + 256 + st * (GSTAGE_BYTES / 4);
        const unsigned* As_lo = As_hi + 4096;
        const unsigned* Bs_hi = As_hi + 8192;
        const unsigned* Bs_lo = As_hi + 12288;

#pragma unroll
        for (int s = 0; s < 4; s++) {
            const int g0 = (((2 * s)     ^ lg) << 2) + lc;
            const int g1 = (((2 * s + 1) ^ lg) << 2) + lc;
            unsigned ah[2][4], al[2][4];
#pragma unroll
            for (int i = 0; i < 2; i++) {
                int r0 = (wm + 16 * i + lg) * 32;
                ah[i][0] = As_hi[r0 + g0];        al[i][0] = As_lo[r0 + g0];
                ah[i][1] = As_hi[r0 + 256 + g0];  al[i][1] = As_lo[r0 + 256 + g0];
                ah[i][2] = As_hi[r0 + g1];        al[i][2] = As_lo[r0 + g1];
                ah[i][3] = As_hi[r0 + 256 + g1];  al[i][3] = As_lo[r0 + 256 + g1];
            }
            unsigned bh[4][2], bl[4][2];
#pragma unroll
            for (int j = 0; j < 4; j++) {
                int rj = (wn + 8 * j + lg) * 32;
                bh[j][0] = Bs_hi[rj + g0];        bh[j][1] = Bs_hi[rj + g1];
                bl[j][0] = Bs_lo[rj + g0];        bl[j][1] = Bs_lo[rj + g1];
            }
#pragma unroll
            for (int i = 0; i < 2; i++)
#pragma unroll
                for (int j = 0; j < 4; j++) {
                    mma_bf16(acc[i][j], ah[i], bh[j]);
                    mma_bf16(acc[i][j], ah[i], bl[j]);
                    mma_bf16(acc[i][j], al[i], bh[j]);
                }
        }
        __syncthreads();
        if (ci + 3 < nk && tid == 0) issue(ci + 3, st);
    }

    const int ncta = cCol * 128;
#pragma unroll
    for (int i = 0; i < 2; i++) {
        int m0 = cRow * 128 + wm + 16 * i + lg;
#pragma unroll
        for (int j = 0; j < 4; j++) {
            int n = ncta + wn + 8 * j + 2 * lc;
            float2 bv = *reinterpret_cast<const float2*>(&bias[n]);
            {
                int bb = m0 >> 10, tt = m0 & 1023;
                float* orow = &out[(size_t)((tt << 6) + bb) << 11];
                float2 r = { acc[i][j][0] + bv.x, acc[i][j][1] + bv.y };
                *reinterpret_cast<float2*>(&orow[n]) = r;
            }
            {
                int m1 = m0 + 8;
                int bb = m1 >> 10, tt = m1 & 1023;
                float* orow = &out[(size_t)((tt << 6) + bb) << 11];
                float2 r = { acc[i][j][2] + bv.x, acc[i][j][3] + bv.y };
                *reinterpret_cast<float2*>(&orow[n]) = r;
            }
        }
    }
}

// ---------------------------------------------------------------------------
__global__ void reset_state()
{
    int i = blockIdx.x * 512 + threadIdx.x;   // 64 x 512 = 32768 = B*H
    g_hhi[0][i] = __nv_bfloat16(0.f);
    g_hlo[0][i] = __nv_bfloat16(0.f);
    if (i < 4 * 32) g_barG[i] = 0u;
}

// ---------------------------------------------------------------------------
// Tensor-core persistent LSTM recurrence — producer-packed bf16 h planes,
// cp.async staging (no consumer-side conversion). Fast-math gates.
// ---------------------------------------------------------------------------
#define SB_HI 0
#define SB_LO 16640
#define SA_HI 33280
#define SA_LO 37440
#define SRB   41600
#define SXGB  51840
#define REC_WORDS 52864
#define REC_SMEM (REC_WORDS * 4)   // 211456 B

__device__ __forceinline__ float fsig_(float x) {
    return __fdividef(1.f, 1.f + __expf(-x));
}
__device__ __forceinline__ float ftanh_(float x) {
    return 1.f - __fdividef(2.f, __expf(2.f * x) + 1.f);
}

__global__ __launch_bounds__(256, 1) void lstm_rec_tc(
    const float* __restrict__ xgp,   // [T][B][2048]
    float* __restrict__ hout)        // [B][T][512]
{
    extern __shared__ unsigned smw[];
    float* smf = reinterpret_cast<float*>(smw);

    const int tid = threadIdx.x;
    const int ug  = blockIdx.x & 31;
    const int bq  = blockIdx.x >> 5;
    const int u0  = ug * 16;
    const int b0  = bq * 16;

    unsigned sbase;
    {
        unsigned long long t64;
        asm("cvta.to.shared.u64 %0, %1;" : "=l"(t64) : "l"(smw));
        sbase = (unsigned)t64;
    }

    // load Wh^T slice (64 rows x 512 bf16, hi+lo), once
    for (int i = tid; i < 64 * 64; i += 256) {
        int r = i >> 6, chunk = i & 63;
        int gate = r >> 4, un = r & 15;
        size_t gR = (size_t)(gate * Hz + u0 + un) * 512;
        unsigned doff = (unsigned)(r * 260 + chunk * 4) * 4u;
        CP_ASYNC16(sbase + (SB_HI * 4u) + doff, g_WhiT + gR + chunk * 8);
        CP_ASYNC16(sbase + (SB_LO * 4u) + doff, g_WloT + gR + chunk * 8);
    }
    CP_COMMIT();
    CP_WAIT0();
    __syncthreads();

    const int wid  = tid >> 5;
    const int lane = tid & 31;
    const int lg   = lane >> 2;
    const int lc   = lane & 3;
    const int sb   = tid >> 4;            // stage row 0..15
    const int sq   = tid & 15;            // 4 chunks of 16B per plane
    const int fu   = tid & 15;
    const int fbL  = tid >> 4;
    const int xrow = tid >> 4;
    const int xseg = tid & 15;
    const int xgate = xseg >> 2;
    const int xun   = (xseg & 3) * 4;

    unsigned* myBar = &g_barG[bq * 32];

    float creg = 0.f;

    for (int t = 0; t < Tz; t++) {
        // ---- stage: cp.async xg tile + h hi/lo planes (no ALU, no reg chain)
        {
            const float* src = &xgp[(size_t)((t << 6) + b0 + xrow) * Gz + (xgate << 9) + u0 + xun];
            CP_ASYNC16(sbase + (unsigned)(SXGB + xrow * 64 + xseg * 4) * 4u, src);

            const __nv_bfloat16* hh = &g_hhi[t & 1][(b0 + sb) * 512];
            const __nv_bfloat16* hl = &g_hlo[t & 1][(b0 + sb) * 512];
            unsigned rowHi = sbase + SA_HI * 4u + (unsigned)sb * 1040u;
            unsigned rowLo = sbase + SA_LO * 4u + (unsigned)sb * 1040u;
#pragma unroll
            for (int i = 0; i < 4; i++) {
                int c = sq * 4 + i;                 // 16B chunk 0..63
                CP_ASYNC16(rowHi + (unsigned)c * 16u, hh + c * 8);
                CP_ASYNC16(rowLo + (unsigned)c * 16u, hl + c * 8);
            }
            CP_COMMIT();
        }
        CP_WAIT0();
        __syncthreads();

        // mma: warp wid handles k16 steps [wid*4, wid*4+4), full N
        float acc[8][4];
#pragma unroll
        for (int j = 0; j < 8; j++)
#pragma unroll
            for (int r = 0; r < 4; r++) acc[j][r] = 0.f;

#pragma unroll
        for (int sl = 0; sl < 4; sl++) {
            int s = wid * 4 + sl;
            int offA = lg * 260 + 8 * s + lc;
            unsigned ah[4], al[4];
            ah[0] = smw[SA_HI + offA];        al[0] = smw[SA_LO + offA];
            ah[1] = smw[SA_HI + offA + 2080]; al[1] = smw[SA_LO + offA + 2080];
            ah[2] = smw[SA_HI + offA + 4];    al[2] = smw[SA_LO + offA + 4];
            ah[3] = smw[SA_HI + offA + 2084]; al[3] = smw[SA_LO + offA + 2084];
#pragma unroll
            for (int j = 0; j < 8; j++) {
                int offB = (8 * j + lg) * 260 + 8 * s + lc;
                unsigned bh[2] = { smw[SB_HI + offB], smw[SB_HI + offB + 4] };
                unsigned bl[2] = { smw[SB_LO + offB], smw[SB_LO + offB + 4] };
                mma_bf16(acc[j], ah, bh);
                mma_bf16(acc[j], ah, bl);
                mma_bf16(acc[j], al, bh);
            }
        }

        // write k-partials
#pragma unroll
        for (int j = 0; j < 8; j++) {
            int c0 = 8 * j + 2 * lc;
            int base = SRB + wid * 1280;
            smf[base + c0 * 20 + lg]            = acc[j][0];
            smf[base + (c0 + 1) * 20 + lg]      = acc[j][1];
            smf[base + c0 * 20 + lg + 8]        = acc[j][2];
            smf[base + (c0 + 1) * 20 + lg + 8]  = acc[j][3];
        }
        __syncthreads();

        // finalize (fast-math gates)
        float gv[4];
#pragma unroll
        for (int g = 0; g < 4; g++) {
            int c = (g << 4) + fu;
            float s = 0.f;
#pragma unroll
            for (int kq = 0; kq < 8; kq++) s += smf[SRB + kq * 1280 + c * 20 + fbL];
            gv[g] = s + smf[SXGB + (fbL << 6) + c];
        }
        float ig = fsig_(gv[0]);
        float fg = fsig_(gv[1]);
        float gg = ftanh_(gv[2]);
        float og = fsig_(gv[3]);
        creg = fg * creg + ig * gg;
        float hv = og * ftanh_(creg);

        // producer-side bf16 split (converted once, consumed by 32 CTAs)
        int gb = b0 + fbL;
        __nv_bfloat16 hhi = __float2bfloat16(hv);
        __nv_bfloat16 hlo = __float2bfloat16(hv - __bfloat162float(hhi));
        g_hhi[(t & 1) ^ 1][gb * 512 + u0 + fu] = hhi;
        g_hlo[(t & 1) ^ 1][gb * 512 + u0 + fu] = hlo;

        // group-local barrier: release first; hout store rides the wait window
        __syncthreads();
        if (tid == 0) {
            asm volatile("red.release.gpu.global.add.u32 [%0], 1;" :: "l"(myBar) : "memory");
        }
        hout[(size_t)((gb << 10) + t) * Hz + u0 + fu] = hv;   // off critical path
        if (tid == 0) {
            unsigned tgt = (unsigned)(t + 1) * 32u;
            unsigned v;
            do {
                asm volatile("ld.acquire.gpu.global.u32 %0, [%1];" : "=r"(v) : "l"(myBar) : "memory");
            } while (v < tgt);
        }
        __syncthreads();
    }
}

// ---------------------------------------------------------------------------
// BatchNorm (deterministic two-stage) + head (proven)
// ---------------------------------------------------------------------------
__global__ void bn_partial(const float* __restrict__ h)
{
    int f = blockIdx.x * 128 + threadIdx.x;
    int chunk = blockIdx.y;
    const float* p = h + (size_t)chunk * (BT / NCHUNK) * Hz + f;
    float s = 0.f, s2 = 0.f;
    for (int r = 0; r < BT / NCHUNK; r++) {
        float v = p[(size_t)r * Hz];
        s += v; s2 += v * v;
    }
    g_ps [chunk * Hz + f] = s;
    g_ps2[chunk * Hz + f] = s2;
}

__global__ void bn_finalize(const float* __restrict__ scale, const float* __restrict__ bias)
{
    int f = blockIdx.x * 128 + threadIdx.x;
    float s = 0.f, s2 = 0.f;
    for (int c = 0; c < NCHUNK; c++) { s += g_ps[c * Hz + f]; s2 += g_ps2[c * Hz + f]; }
    float mean = s * (1.f / 65536.f);
    float var  = s2 * (1.f / 65536.f) - mean * mean;
    float rstd = rsqrtf(var + 1e-5f);
    float a = rstd * scale[f];
    g_bnA[f] = a;
    g_bnB[f] = bias[f] - mean * a;
}

__global__ void head_kernel(const float* __restrict__ h2,
                            const float* __restrict__ Wd1, const float* __restrict__ bd1,
                            const float* __restrict__ Wd2, const float* __restrict__ bd2,
                            float* __restrict__ out)
{
    __shared__ float sh[512];
    __shared__ float sy[16];
    int b = blockIdx.x;
    int tid = threadIdx.x;
    float v = h2[((size_t)b * 1024 + 1023) * Hz + tid];
    sh[tid] = v * g_bnA[tid] + g_bnB[tid];
    __syncthreads();

    int w = tid >> 5, lane = tid & 31;
    float s = 0.f;
    for (int f = lane; f < 512; f += 32) s += sh[f] * Wd1[f * 16 + w];
#pragma unroll
    for (int off = 16; off; off >>= 1) s += __shfl_down_sync(0xffffffffu, s, off);
    if (lane == 0) sy[w] = fmaxf(s + bd1[w], 0.f);
    __syncthreads();
    if (tid == 0) {
        float o = bd2[0];
#pragma unroll
        for (int j = 0; j < 16; j++) o += sy[j] * Wd2[j];
        out[b] = o;
    }
}

// ---------------------------------------------------------------------------
extern "C" void kernel_launch(void* const* d_in, const int* in_sizes, int n_in,
                              void* d_out, int out_size)
{
    const float* x    = (const float*)d_in[0];
    const float* Wx1  = (const float*)d_in[1];
    const float* Wh1  = (const float*)d_in[2];
    const float* b1   = (const float*)d_in[3];
    const float* s1   = (const float*)d_in[4];
    const float* bi1  = (const float*)d_in[5];
    const float* Wx2  = (const float*)d_in[6];
    const float* Wh2  = (const float*)d_in[7];
    const float* b2   = (const float*)d_in[8];
    const float* s2   = (const float*)d_in[9];
    const float* bi2  = (const float*)d_in[10];
    const float* Wd1  = (const float*)d_in[11];
    const float* bd1  = (const float*)d_in[12];
    const float* Wd2  = (const float*)d_in[13];
    const float* bd2  = (const float*)d_in[14];
    float* out = (float*)d_out;

    float *xg, *h1, *h2;
    cudaGetSymbolAddress((void**)&xg, g_xg);
    cudaGetSymbolAddress((void**)&h1, g_h1);
    cudaGetSymbolAddress((void**)&h2, g_h2);

    cudaFuncSetAttribute(lstm_rec_tc, cudaFuncAttributeMaxDynamicSharedMemorySize, REC_SMEM);
    cudaFuncSetAttribute(sgemm_bf16, cudaFuncAttributeMaxDynamicSharedMemorySize, GEMM_SMEM);

    // ---- layer 1 (K=128: ksh=5, nk=2); sgemm stays launch #4 (profiled) ----
    split_A<<<(BT * Dz / 4 + 255) / 256, 256>>>(x, BT * Dz / 4, 5, 2);
    split_W_pk<<<(Gz * Dz / 4 + 255) / 256, 256>>>(Wx1, Dz, 2);
    split_W<<<dim3(64, Hz / 32), 256>>>(Wh1, Hz);
    sgemm_bf16<<<dim3(16, 512), 512, GEMM_SMEM>>>(b1, xg, Dz);      // launch #4
    reset_state<<<64, 512>>>();
    lstm_rec_tc<<<128, 256, REC_SMEM>>>(xg, h1);
    bn_partial<<<dim3(4, NCHUNK), 128>>>(h1);
    bn_finalize<<<4, 128>>>(s1, bi1);

    // ---- layer 2 (K=512: ksh=7, nk=8) ----
    split_A_bn<<<(BT * Hz / 4 + 255) / 256, 256>>>(h1, BT * Hz / 4, 7, 8);
    split_W_pk<<<(Gz * Hz / 4 + 255) / 256, 256>>>(Wx2, Hz, 8);
    sgemm_bf16<<<dim3(16, 512), 512, GEMM_SMEM>>>(b2, xg, Hz);
    split_W<<<dim3(64, Hz / 32), 256>>>(Wh2, Hz);
    reset_state<<<64, 512>>>();
    lstm_rec_tc<<<128, 256, REC_SMEM>>>(xg, h2);
    bn_partial<<<dim3(4, NCHUNK), 128>>>(h2);
    bn_finalize<<<4, 128>>>(s2, bi2);

    // head (applies bn2 to last timestep only)
    head_kernel<<<64, 512>>>(h2, Wd1, bd1, Wd2, bd2, out);
}